// round 1
// baseline (speedup 1.0000x reference)
#include <cuda_runtime.h>
#include <math.h>

// Problem constants
#define B_    64
#define T_    8192
#define DIN   20
#define DOUT  128
#define NROWS ((size_t)B_ * T_)

// Scratch for features [B*T, 20] (device global — no allocation allowed)
__device__ float g_feats[NROWS * DIN];

// ---------------------------------------------------------------------------
// Kernel A: per-timestep features + exact parallel EMA scan (two alphas).
// One block per batch row (64 blocks), 512 threads, 16 timesteps per thread.
// EMA recurrence acc = a*acc + (1-a)*x is an affine map per chunk; we scan
// the affine maps (A,B) across the block to get exact incoming accumulators.
// ---------------------------------------------------------------------------
__global__ void __launch_bounds__(512) feat_kernel(
    const float* __restrict__ gaze,     // [B,T,2]
    const float* __restrict__ lwx, const float* __restrict__ phx,
    const float* __restrict__ lwy, const float* __restrict__ phy,
    const float* __restrict__ p_logthr, const float* __restrict__ p_invT,
    float* __restrict__ feats)
{
    const int CH = T_ / 512;            // 16
    const int b    = blockIdx.x;
    const int tid  = threadIdx.x;
    const int lane = tid & 31;
    const int warp = tid >> 5;          // 0..15
    const int t0   = tid * CH;

    const float2* gz = reinterpret_cast<const float2*>(gaze) + (size_t)b * T_;

    const float thr    = expf(p_logthr[0]);
    const float invT   = p_invT[0];
    const float inv_dt = 240.0f;

    // Load chunk (+2 left-clamped halo) into registers
    float2 xb[CH + 2];
    xb[0] = gz[max(t0 - 2, 0)];
    xb[1] = gz[max(t0 - 1, 0)];
#pragma unroll
    for (int i = 0; i < CH; i++) xb[i + 2] = gz[t0 + i];

    // Pass 1: chunk-local affine transform of the two EMAs (acc_in = 0)
    float Af = 1.0f, Bf = 0.0f, As = 1.0f, Bs = 0.0f;
#pragma unroll
    for (int i = 0; i < CH; i++) {
        float vx = (xb[i + 2].x - xb[i + 1].x) * inv_dt;
        float vy = (xb[i + 2].y - xb[i + 1].y) * inv_dt;
        float sp = sqrtf(vx * vx + vy * vy);
        float gate = 1.0f / (1.0f + expf(-invT * (sp - thr)));
        Bf = 0.8f  * Bf + 0.2f  * gate;  Af *= 0.8f;
        Bs = 0.95f * Bs + 0.05f * gate;  As *= 0.95f;
    }

    // Block-wide inclusive scan of affine maps: compose(p,q)(x) = q(p(x))
    __shared__ float sAf[16], sBf[16], sAs[16], sBs[16];
    const unsigned full = 0xffffffffu;
    float iAf = Af, iBf = Bf, iAs = As, iBs = Bs;
#pragma unroll
    for (int d = 1; d < 32; d <<= 1) {
        float pa = __shfl_up_sync(full, iAf, d);
        float pb = __shfl_up_sync(full, iBf, d);
        float qa = __shfl_up_sync(full, iAs, d);
        float qb = __shfl_up_sync(full, iBs, d);
        if (lane >= d) {
            iBf = iAf * pb + iBf;  iAf *= pa;
            iBs = iAs * qb + iBs;  iAs *= qa;
        }
    }
    // exclusive within warp
    float eAf = __shfl_up_sync(full, iAf, 1), eBf = __shfl_up_sync(full, iBf, 1);
    float eAs = __shfl_up_sync(full, iAs, 1), eBs = __shfl_up_sync(full, iBs, 1);
    if (lane == 0) { eAf = 1.0f; eBf = 0.0f; eAs = 1.0f; eBs = 0.0f; }
    if (lane == 31) { sAf[warp] = iAf; sBf[warp] = iBf; sAs[warp] = iAs; sBs[warp] = iBs; }
    __syncthreads();

    // warp-level prefix (only 16 aggregates; sequential compose is cheap)
    float pBf = 0.0f, pBs = 0.0f;
    for (int w = 0; w < warp; w++) {
        pBf = sAf[w] * pBf + sBf[w];
        pBs = sAs[w] * pBs + sBs[w];
    }
    // incoming accumulators for this thread's chunk (applied to acc=0)
    float accf = eAf * pBf + eBf;
    float accs = eAs * pBs + eBs;

    // Pass 2: full features + EMA outputs
    const float wx0 = expf(lwx[0]), wx1 = expf(lwx[1]);
    const float px0 = phx[0],       px1 = phx[1];
    const float wy0 = expf(lwy[0]), wy1 = expf(lwy[1]);
    const float py0 = phy[0],       py1 = phy[1];
    const float twopi = 6.283185307179586f;

    float* fp = feats + ((size_t)b * T_ + t0) * DIN;
#pragma unroll
    for (int i = 0; i < CH; i++) {
        float x  = xb[i + 2].x, y = xb[i + 2].y;
        float vx = (x - xb[i + 1].x) * inv_dt;
        float vy = (y - xb[i + 1].y) * inv_dt;
        float pvx = (xb[i + 1].x - xb[i].x) * inv_dt;
        float pvy = (xb[i + 1].y - xb[i].y) * inv_dt;
        float ax = (vx - pvx) * inv_dt;
        float ay = (vy - pvy) * inv_dt;
        float sp  = sqrtf(vx * vx + vy * vy);
        float isp = 1.0f / (sp + 1e-6f);
        float gate = 1.0f / (1.0f + expf(-invT * (sp - thr)));
        accf = 0.8f  * accf + 0.2f  * gate;
        accs = 0.95f * accs + 0.05f * gate;

        float s0, c0, s1, c1, u0, d0, u1, d1;
        sincosf(twopi * x * wx0 + px0, &s0, &c0);
        sincosf(twopi * x * wx1 + px1, &s1, &c1);
        sincosf(twopi * y * wy0 + py0, &u0, &d0);
        sincosf(twopi * y * wy1 + py1, &u1, &d1);

        fp[0]  = s0;  fp[1]  = s1;  fp[2]  = c0;  fp[3]  = c1;
        fp[4]  = u0;  fp[5]  = u1;  fp[6]  = d0;  fp[7]  = d1;
        fp[8]  = vx;  fp[9]  = vy;  fp[10] = sp;
        fp[11] = vx * isp;            fp[12] = vy * isp;
        fp[13] = ax;  fp[14] = ay;
        fp[15] = (vx * ax + vy * ay) * isp;
        fp[16] = (vx * ay - vy * ax) * isp;
        fp[17] = gate; fp[18] = accf; fp[19] = accs;
        fp += DIN;
    }
}

// ---------------------------------------------------------------------------
// Kernel B: fused  out = gelu( gelu(feats@W1 + b1) @ W2 + b2 )
// 128-row tile per block, 256 threads in 16x16, 8x8 register micro-tile.
// W1, W2, feats tile, h1 tile all resident in shared memory (~150 KB).
// ---------------------------------------------------------------------------
__device__ __forceinline__ float gelu_exact(float x) {
    return 0.5f * x * (1.0f + erff(x * 0.70710678118654752f));
}

__global__ void __launch_bounds__(256) fused_mlp_kernel(
    const float* __restrict__ feats,
    const float* __restrict__ W1, const float* __restrict__ b1,
    const float* __restrict__ W2, const float* __restrict__ b2,
    float* __restrict__ out)
{
    extern __shared__ float sm[];
    float* W1s = sm;                  // 20*128
    float* W2s = W1s + DIN * DOUT;    // 128*128
    float* fs  = W2s + DOUT * DOUT;   // 128*20
    float* h1s = fs  + 128 * DIN;     // 128*128
    float* b1s = h1s + 128 * DOUT;    // 128
    float* b2s = b1s + DOUT;          // 128

    const int tid  = threadIdx.x;
    const size_t row0 = (size_t)blockIdx.x * 128;

    for (int i = tid; i < DIN * DOUT; i += 256) W1s[i] = W1[i];
    for (int i = tid; i < DOUT * DOUT; i += 256) W2s[i] = W2[i];
    if (tid < DOUT) { b1s[tid] = b1[tid]; b2s[tid] = b2[tid]; }
    for (int i = tid; i < 128 * DIN; i += 256) fs[i] = feats[row0 * DIN + i];
    __syncthreads();

    const int tx = tid & 15;   // col group: cols tx*8 .. tx*8+7
    const int ty = tid >> 4;   // row group: rows ty*8 .. ty*8+7

    float acc[8][8];

    // ----- Stage 1: h1 = gelu(feats @ W1 + b1), K = 20 -----
#pragma unroll
    for (int i = 0; i < 8; i++)
#pragma unroll
        for (int j = 0; j < 8; j++) acc[i][j] = b1s[tx * 8 + j];

#pragma unroll 4
    for (int k = 0; k < DIN; k++) {
        float av[8];
#pragma unroll
        for (int i = 0; i < 8; i++) av[i] = fs[(ty * 8 + i) * DIN + k];
        float4 w0 = *reinterpret_cast<const float4*>(&W1s[k * DOUT + tx * 8]);
        float4 w1 = *reinterpret_cast<const float4*>(&W1s[k * DOUT + tx * 8 + 4]);
        float wv[8] = {w0.x, w0.y, w0.z, w0.w, w1.x, w1.y, w1.z, w1.w};
#pragma unroll
        for (int i = 0; i < 8; i++)
#pragma unroll
            for (int j = 0; j < 8; j++) acc[i][j] += av[i] * wv[j];
    }
#pragma unroll
    for (int i = 0; i < 8; i++) {
        float4 o0, o1;
        o0.x = gelu_exact(acc[i][0]); o0.y = gelu_exact(acc[i][1]);
        o0.z = gelu_exact(acc[i][2]); o0.w = gelu_exact(acc[i][3]);
        o1.x = gelu_exact(acc[i][4]); o1.y = gelu_exact(acc[i][5]);
        o1.z = gelu_exact(acc[i][6]); o1.w = gelu_exact(acc[i][7]);
        *reinterpret_cast<float4*>(&h1s[(ty * 8 + i) * DOUT + tx * 8])     = o0;
        *reinterpret_cast<float4*>(&h1s[(ty * 8 + i) * DOUT + tx * 8 + 4]) = o1;
    }
    __syncthreads();

    // ----- Stage 2: out = gelu(h1 @ W2 + b2), K = 128 -----
#pragma unroll
    for (int i = 0; i < 8; i++)
#pragma unroll
        for (int j = 0; j < 8; j++) acc[i][j] = b2s[tx * 8 + j];

#pragma unroll 2
    for (int k = 0; k < DOUT; k++) {
        float av[8];
#pragma unroll
        for (int i = 0; i < 8; i++) av[i] = h1s[(ty * 8 + i) * DOUT + k];
        float4 w0 = *reinterpret_cast<const float4*>(&W2s[k * DOUT + tx * 8]);
        float4 w1 = *reinterpret_cast<const float4*>(&W2s[k * DOUT + tx * 8 + 4]);
        float wv[8] = {w0.x, w0.y, w0.z, w0.w, w1.x, w1.y, w1.z, w1.w};
#pragma unroll
        for (int i = 0; i < 8; i++)
#pragma unroll
            for (int j = 0; j < 8; j++) acc[i][j] += av[i] * wv[j];
    }

#pragma unroll
    for (int i = 0; i < 8; i++) {
        float4 o0, o1;
        o0.x = gelu_exact(acc[i][0]); o0.y = gelu_exact(acc[i][1]);
        o0.z = gelu_exact(acc[i][2]); o0.w = gelu_exact(acc[i][3]);
        o1.x = gelu_exact(acc[i][4]); o1.y = gelu_exact(acc[i][5]);
        o1.z = gelu_exact(acc[i][6]); o1.w = gelu_exact(acc[i][7]);
        float* op = out + (row0 + (size_t)(ty * 8 + i)) * DOUT + tx * 8;
        *reinterpret_cast<float4*>(op)     = o0;
        *reinterpret_cast<float4*>(op + 4) = o1;
    }
}

// ---------------------------------------------------------------------------
extern "C" void kernel_launch(void* const* d_in, const int* in_sizes, int n_in,
                              void* d_out, int out_size)
{
    const float* gaze    = (const float*)d_in[0];
    const float* lwx     = (const float*)d_in[1];
    const float* phx     = (const float*)d_in[2];
    const float* lwy     = (const float*)d_in[3];
    const float* phy     = (const float*)d_in[4];
    const float* logthr  = (const float*)d_in[5];
    const float* invT    = (const float*)d_in[6];
    const float* W1      = (const float*)d_in[7];
    const float* b1      = (const float*)d_in[8];
    const float* W2      = (const float*)d_in[9];
    const float* b2      = (const float*)d_in[10];
    float* out = (float*)d_out;

    float* feats;
    cudaGetSymbolAddress((void**)&feats, g_feats);

    feat_kernel<<<B_, 512>>>(gaze, lwx, phx, lwy, phy, logthr, invT, feats);

    const size_t smem = (size_t)(DIN * DOUT + DOUT * DOUT + 128 * DIN +
                                 128 * DOUT + 2 * DOUT) * sizeof(float); // 152576 B
    cudaFuncSetAttribute(fused_mlp_kernel,
                         cudaFuncAttributeMaxDynamicSharedMemorySize, (int)smem);
    fused_mlp_kernel<<<(int)(NROWS / 128), 256, smem>>>(feats, W1, b1, W2, b2, out);
}

// round 2
// speedup vs baseline: 1.3194x; 1.3194x over previous
#include <cuda_runtime.h>
#include <math.h>

// Problem constants
#define B_    64
#define T_    8192
#define DIN   20
#define DOUT  128
#define NROWS ((size_t)B_ * T_)
#define WARM  512            // EMA warm-up window: 0.95^512 ~ 4e-12

// ---------------------------------------------------------------------------
// tf32 helpers
// ---------------------------------------------------------------------------
__device__ __forceinline__ unsigned f2tf32(float x) {
    unsigned u; asm("cvt.rna.tf32.f32 %0, %1;" : "=r"(u) : "f"(x)); return u;
}
__device__ __forceinline__ void split_tf32(float x, unsigned& hi, unsigned& lo) {
    unsigned h = f2tf32(x);
    float r = x - __uint_as_float(h);
    hi = h; lo = f2tf32(r);
}

#define MMA_TF32(d, a, b)                                                     \
    asm volatile(                                                             \
        "mma.sync.aligned.m16n8k8.row.col.f32.tf32.tf32.f32 "                 \
        "{%0,%1,%2,%3}, {%4,%5,%6,%7}, {%8,%9}, {%0,%1,%2,%3};"               \
        : "+f"(d[0]), "+f"(d[1]), "+f"(d[2]), "+f"(d[3])                      \
        : "r"(a[0]), "r"(a[1]), "r"(a[2]), "r"(a[3]), "r"(b[0]), "r"(b[1]))

__device__ __forceinline__ float gelu_exact(float x) {
    return 0.5f * x * (1.0f + erff(x * 0.70710678118654752f));
}

// ---------------------------------------------------------------------------
// Smem layout (floats)
// ---------------------------------------------------------------------------
#define SW2   0                         // W2 padded [128][132]
#define SH1   (SW2 + 128 * 132)         // h1        [128][132]
#define SW1   (SH1 + 128 * 132)         // W1 padded [32][132]
#define SFS   (SW1 + 32 * 132)          // feats     [128][36]
#define SB1   (SFS + 128 * 36)          // b1 [128]
#define SB2   (SB1 + 128)               // b2 [128]
#define SGZ   (SB2 + 128)               // gaze float2[644] -> 1288 floats
#define SSCN  (SGZ + 1288)              // scan scratch [32]
#define SMEM_FLOATS (SSCN + 32)         // = 44200 floats = 176800 B

// ---------------------------------------------------------------------------
// Fused kernel: features (+EMA warm-up scan) -> gelu(X@W1+b1) -> gelu(..@W2+b2)
// grid = 4096 (64 batch rows x 64 tiles of 128 timesteps), 256 threads.
// ---------------------------------------------------------------------------
__global__ void __launch_bounds__(256, 1) fused_gaze_kernel(
    const float* __restrict__ gaze,
    const float* __restrict__ lwx, const float* __restrict__ phx,
    const float* __restrict__ lwy, const float* __restrict__ phy,
    const float* __restrict__ p_logthr, const float* __restrict__ p_invT,
    const float* __restrict__ W1, const float* __restrict__ b1,
    const float* __restrict__ W2, const float* __restrict__ b2,
    float* __restrict__ out)
{
    extern __shared__ float sm[];
    float*  W2s = sm + SW2;
    float*  h1s = sm + SH1;
    float*  W1s = sm + SW1;
    float*  fs  = sm + SFS;
    float*  b1s = sm + SB1;
    float*  b2s = sm + SB2;
    float2* sg  = reinterpret_cast<float2*>(sm + SGZ);
    float*  scn = sm + SSCN;

    const int tid = threadIdx.x;
    const int bIdx = blockIdx.x >> 6;         // batch row
    const int t0   = (blockIdx.x & 63) << 7;  // tile start timestep
    const int ts   = max(t0 - WARM, 0);       // EMA warm-up start
    const int ts2  = max(ts - 2, 0);          // gaze halo start
    const int E    = t0 + 128 - ts;           // elements in scan
    const int NG   = t0 + 128 - ts2;          // gaze elements to load

    // ---- cooperative loads ----
    const float2* gz = reinterpret_cast<const float2*>(gaze) + (size_t)bIdx * T_;
    for (int i = tid; i < NG; i += 256) sg[i] = gz[ts2 + i];
    for (int i = tid; i < 32 * 132; i += 256) {
        int k = i / 132, n = i - k * 132;
        W1s[i] = (k < DIN && n < DOUT) ? W1[k * DOUT + n] : 0.0f;
    }
    for (int i = tid; i < DOUT * DOUT; i += 256) {
        int k = i >> 7, n = i & 127;
        W2s[k * 132 + n] = W2[i];
    }
    if (tid < DOUT) { b1s[tid] = b1[tid]; b2s[tid] = b2[tid]; }

    const float thr  = expf(p_logthr[0]);
    const float invT = p_invT[0];
    const float inv_dt = 240.0f;
    __syncthreads();

    // ---- pass 1: gates + chunk-local affine maps (3 elements / thread) ----
    const int lane = tid & 31, warp = tid >> 5;
    float gv[3];
    float Af = 1.0f, Bf = 0.0f, As = 1.0f, Bs = 0.0f;
#pragma unroll
    for (int i = 0; i < 3; i++) {
        int e = tid * 3 + i;
        if (e < E) {
            int t  = ts + e;
            int i2 = t - ts2;
            float2 xc = sg[i2];
            float2 x1 = sg[max(i2 - 1, 0)];
            float vx = (xc.x - x1.x) * inv_dt;
            float vy = (xc.y - x1.y) * inv_dt;
            float sp = sqrtf(vx * vx + vy * vy);
            float g  = 1.0f / (1.0f + expf(-invT * (sp - thr)));
            gv[i] = g;
            Bf = 0.8f  * Bf + 0.2f  * g;  Af *= 0.8f;
            Bs = 0.95f * Bs + 0.05f * g;  As *= 0.95f;
        }
    }

    // warp inclusive affine scan
    const unsigned full = 0xffffffffu;
    float iAf = Af, iBf = Bf, iAs = As, iBs = Bs;
#pragma unroll
    for (int d = 1; d < 32; d <<= 1) {
        float pa = __shfl_up_sync(full, iAf, d);
        float pb = __shfl_up_sync(full, iBf, d);
        float qa = __shfl_up_sync(full, iAs, d);
        float qb = __shfl_up_sync(full, iBs, d);
        if (lane >= d) {
            iBf = iAf * pb + iBf;  iAf *= pa;
            iBs = iAs * qb + iBs;  iAs *= qa;
        }
    }
    float eAf = __shfl_up_sync(full, iAf, 1), eBf = __shfl_up_sync(full, iBf, 1);
    float eAs = __shfl_up_sync(full, iAs, 1), eBs = __shfl_up_sync(full, iBs, 1);
    if (lane == 0) { eAf = 1.0f; eBf = 0.0f; eAs = 1.0f; eBs = 0.0f; }
    if (lane == 31) {
        scn[warp] = iAf; scn[8 + warp] = iBf; scn[16 + warp] = iAs; scn[24 + warp] = iBs;
    }
    __syncthreads();
    float pBf = 0.0f, pBs = 0.0f;
    for (int w = 0; w < warp; w++) {
        pBf = scn[w] * pBf + scn[8 + w];
        pBs = scn[16 + w] * pBs + scn[24 + w];
    }
    float accf = eAf * pBf + eBf;
    float accs = eAs * pBs + eBs;

    // ---- pass 2: features for tile rows ----
    const float wx0 = expf(lwx[0]), wx1 = expf(lwx[1]);
    const float px0 = phx[0],       px1 = phx[1];
    const float wy0 = expf(lwy[0]), wy1 = expf(lwy[1]);
    const float py0 = phy[0],       py1 = phy[1];
    const float twopi = 6.283185307179586f;

#pragma unroll
    for (int i = 0; i < 3; i++) {
        int e = tid * 3 + i;
        if (e < E) {
            accf = 0.8f  * accf + 0.2f  * gv[i];
            accs = 0.95f * accs + 0.05f * gv[i];
            int t = ts + e;
            if (t >= t0) {
                int i2 = t - ts2;
                float2 xc = sg[i2];
                float2 x1 = sg[max(i2 - 1, 0)];
                float2 x2 = sg[max(i2 - 2, 0)];
                float vx  = (xc.x - x1.x) * inv_dt;
                float vy  = (xc.y - x1.y) * inv_dt;
                float pvx = (x1.x - x2.x) * inv_dt;
                float pvy = (x1.y - x2.y) * inv_dt;
                float ax  = (vx - pvx) * inv_dt;
                float ay  = (vy - pvy) * inv_dt;
                float sp  = sqrtf(vx * vx + vy * vy);
                float isp = 1.0f / (sp + 1e-6f);
                float gate = gv[i];
                float s0, c0, s1, c1, u0, d0, u1, d1;
                sincosf(twopi * xc.x * wx0 + px0, &s0, &c0);
                sincosf(twopi * xc.x * wx1 + px1, &s1, &c1);
                sincosf(twopi * xc.y * wy0 + py0, &u0, &d0);
                sincosf(twopi * xc.y * wy1 + py1, &u1, &d1);
                float* fp = fs + (t - t0) * 36;
                fp[0]  = s0;  fp[1]  = s1;  fp[2]  = c0;  fp[3]  = c1;
                fp[4]  = u0;  fp[5]  = u1;  fp[6]  = d0;  fp[7]  = d1;
                fp[8]  = vx;  fp[9]  = vy;  fp[10] = sp;
                fp[11] = vx * isp;  fp[12] = vy * isp;
                fp[13] = ax;  fp[14] = ay;
                fp[15] = (vx * ax + vy * ay) * isp;
                fp[16] = (vx * ay - vy * ax) * isp;
                fp[17] = gate; fp[18] = accf; fp[19] = accs;
#pragma unroll
                for (int z = 20; z < 36; z++) fp[z] = 0.0f;  // K-pad must be clean
            }
        }
    }
    __syncthreads();

    // ---- tensor-core MLP ----
    const int g  = lane >> 2, tg = lane & 3;
    const int wm = warp & 1,  wn = warp >> 1;
    const int mBase = wm * 64, nBase = wn * 32;

    float acc[16][4];

    // Stage 1: h1 = gelu(feats @ W1 + b1), K = 32 (padded), 3xTF32
#pragma unroll
    for (int mt = 0; mt < 4; mt++)
#pragma unroll
        for (int nt = 0; nt < 4; nt++) {
            int f = mt * 4 + nt, col = nBase + nt * 8 + 2 * tg;
            acc[f][0] = b1s[col]; acc[f][1] = b1s[col + 1];
            acc[f][2] = acc[f][0]; acc[f][3] = acc[f][1];
        }

#pragma unroll 1
    for (int kc = 0; kc < 4; kc++) {
        int k0 = kc * 8;
        unsigned Ab[4][4], Al[4][4], Bb[4][2], Bl[4][2];
#pragma unroll
        for (int mt = 0; mt < 4; mt++) {
            int r = mBase + mt * 16 + g;
            split_tf32(fs[r * 36 + k0 + tg],           Ab[mt][0], Al[mt][0]);
            split_tf32(fs[(r + 8) * 36 + k0 + tg],     Ab[mt][1], Al[mt][1]);
            split_tf32(fs[r * 36 + k0 + tg + 4],       Ab[mt][2], Al[mt][2]);
            split_tf32(fs[(r + 8) * 36 + k0 + tg + 4], Ab[mt][3], Al[mt][3]);
        }
#pragma unroll
        for (int nt = 0; nt < 4; nt++) {
            int c = nBase + nt * 8 + g;
            split_tf32(W1s[(k0 + tg) * 132 + c],     Bb[nt][0], Bl[nt][0]);
            split_tf32(W1s[(k0 + tg + 4) * 132 + c], Bb[nt][1], Bl[nt][1]);
        }
#pragma unroll
        for (int mt = 0; mt < 4; mt++)
#pragma unroll
            for (int nt = 0; nt < 4; nt++) {
                int f = mt * 4 + nt;
                MMA_TF32(acc[f], Ab[mt], Bb[nt]);
                MMA_TF32(acc[f], Ab[mt], Bl[nt]);
                MMA_TF32(acc[f], Al[mt], Bb[nt]);
            }
    }

#pragma unroll
    for (int mt = 0; mt < 4; mt++)
#pragma unroll
        for (int nt = 0; nt < 4; nt++) {
            int f = mt * 4 + nt;
            int r = mBase + mt * 16 + g, c = nBase + nt * 8 + 2 * tg;
            h1s[r * 132 + c]           = gelu_exact(acc[f][0]);
            h1s[r * 132 + c + 1]       = gelu_exact(acc[f][1]);
            h1s[(r + 8) * 132 + c]     = gelu_exact(acc[f][2]);
            h1s[(r + 8) * 132 + c + 1] = gelu_exact(acc[f][3]);
        }
    __syncthreads();

    // Stage 2: out = gelu(h1 @ W2 + b2), K = 128, 3xTF32
#pragma unroll
    for (int mt = 0; mt < 4; mt++)
#pragma unroll
        for (int nt = 0; nt < 4; nt++) {
            int f = mt * 4 + nt, col = nBase + nt * 8 + 2 * tg;
            acc[f][0] = b2s[col]; acc[f][1] = b2s[col + 1];
            acc[f][2] = acc[f][0]; acc[f][3] = acc[f][1];
        }

#pragma unroll 1
    for (int kc = 0; kc < 16; kc++) {
        int k0 = kc * 8;
        unsigned Ab[4][4], Al[4][4], Bb[4][2], Bl[4][2];
#pragma unroll
        for (int mt = 0; mt < 4; mt++) {
            int r = mBase + mt * 16 + g;
            split_tf32(h1s[r * 132 + k0 + tg],           Ab[mt][0], Al[mt][0]);
            split_tf32(h1s[(r + 8) * 132 + k0 + tg],     Ab[mt][1], Al[mt][1]);
            split_tf32(h1s[r * 132 + k0 + tg + 4],       Ab[mt][2], Al[mt][2]);
            split_tf32(h1s[(r + 8) * 132 + k0 + tg + 4], Ab[mt][3], Al[mt][3]);
        }
#pragma unroll
        for (int nt = 0; nt < 4; nt++) {
            int c = nBase + nt * 8 + g;
            split_tf32(W2s[(k0 + tg) * 132 + c],     Bb[nt][0], Bl[nt][0]);
            split_tf32(W2s[(k0 + tg + 4) * 132 + c], Bb[nt][1], Bl[nt][1]);
        }
#pragma unroll
        for (int mt = 0; mt < 4; mt++)
#pragma unroll
            for (int nt = 0; nt < 4; nt++) {
                int f = mt * 4 + nt;
                MMA_TF32(acc[f], Ab[mt], Bb[nt]);
                MMA_TF32(acc[f], Ab[mt], Bl[nt]);
                MMA_TF32(acc[f], Al[mt], Bb[nt]);
            }
    }

    // epilogue: gelu + write
    const size_t r0 = (size_t)blockIdx.x * 128;
#pragma unroll
    for (int mt = 0; mt < 4; mt++)
#pragma unroll
        for (int nt = 0; nt < 4; nt++) {
            int f = mt * 4 + nt;
            int r = mBase + mt * 16 + g, c = nBase + nt * 8 + 2 * tg;
            float2 v0 = make_float2(gelu_exact(acc[f][0]), gelu_exact(acc[f][1]));
            float2 v1 = make_float2(gelu_exact(acc[f][2]), gelu_exact(acc[f][3]));
            *reinterpret_cast<float2*>(out + (r0 + r) * 128 + c)       = v0;
            *reinterpret_cast<float2*>(out + (r0 + r + 8) * 128 + c)   = v1;
        }
}

// ---------------------------------------------------------------------------
extern "C" void kernel_launch(void* const* d_in, const int* in_sizes, int n_in,
                              void* d_out, int out_size)
{
    const float* gaze   = (const float*)d_in[0];
    const float* lwx    = (const float*)d_in[1];
    const float* phx    = (const float*)d_in[2];
    const float* lwy    = (const float*)d_in[3];
    const float* phy    = (const float*)d_in[4];
    const float* logthr = (const float*)d_in[5];
    const float* invT   = (const float*)d_in[6];
    const float* W1     = (const float*)d_in[7];
    const float* b1     = (const float*)d_in[8];
    const float* W2     = (const float*)d_in[9];
    const float* b2     = (const float*)d_in[10];
    float* out = (float*)d_out;

    const size_t smem = (size_t)SMEM_FLOATS * sizeof(float);  // 176800 B
    cudaFuncSetAttribute(fused_gaze_kernel,
                         cudaFuncAttributeMaxDynamicSharedMemorySize, (int)smem);
    fused_gaze_kernel<<<(int)(NROWS / 128), 256, smem>>>(
        gaze, lwx, phx, lwy, phy, logthr, invT, W1, b1, W2, b2, out);
}

// round 3
// speedup vs baseline: 1.8764x; 1.4221x over previous
#include <cuda_runtime.h>
#include <math.h>

#define B_    64
#define T_    8192
#define DIN   20
#define DOUT  128
#define NROWS ((size_t)B_ * T_)
#define WARM  512

// device scratch (allocation-free rule)
__device__ float g_gate[NROWS];
__device__ float g_qf[NROWS];
__device__ float g_qs[NROWS];

// ---------------------------------------------------------------------------
__device__ __forceinline__ unsigned f2tf32(float x) {
    unsigned u; asm("cvt.rna.tf32.f32 %0, %1;" : "=r"(u) : "f"(x)); return u;
}
__device__ __forceinline__ void split_tf32(float x, unsigned& hi, unsigned& lo) {
    unsigned h = f2tf32(x);
    hi = h; lo = f2tf32(x - __uint_as_float(h));
}
#define MMA8(d, a, b)                                                         \
    asm volatile(                                                             \
        "mma.sync.aligned.m16n8k8.row.col.f32.tf32.tf32.f32 "                 \
        "{%0,%1,%2,%3}, {%4,%5,%6,%7}, {%8,%9}, {%0,%1,%2,%3};"               \
        : "+f"(d[0]), "+f"(d[1]), "+f"(d[2]), "+f"(d[3])                      \
        : "r"(a[0]), "r"(a[1]), "r"(a[2]), "r"(a[3]), "r"(b[0]), "r"(b[1]))
#define MMA4(d, a, b)                                                         \
    asm volatile(                                                             \
        "mma.sync.aligned.m16n8k4.row.col.f32.tf32.tf32.f32 "                 \
        "{%0,%1,%2,%3}, {%4,%5}, {%6}, {%0,%1,%2,%3};"                        \
        : "+f"(d[0]), "+f"(d[1]), "+f"(d[2]), "+f"(d[3])                      \
        : "r"(a[0]), "r"(a[1]), "r"(b[0]))

__device__ __forceinline__ float gelu_exact(float x) {
    return 0.5f * x * (1.0f + erff(x * 0.70710678118654752f));
}

// ---------------------------------------------------------------------------
// Kernel A: gate + EMA(0.8/0.95) with 512-step warm-up, segment-parallel.
// grid = 64 rows x 4 segments of 2048; 256 threads; affine-map block scan.
// ---------------------------------------------------------------------------
__global__ void __launch_bounds__(256) ema_kernel(
    const float* __restrict__ gaze,
    const float* __restrict__ p_logthr, const float* __restrict__ p_invT,
    float* __restrict__ gate_o, float* __restrict__ qf_o, float* __restrict__ qs_o)
{
    extern __shared__ float sm[];
    float2* sg  = reinterpret_cast<float2*>(sm);       // up to 2561 float2
    float*  sga = sm + 5124;
    float*  sqf = sga + 2560;
    float*  sqs = sqf + 2560;
    float*  scn = sqs + 2560;                          // 32

    const int tid = threadIdx.x;
    const int row = blockIdx.x >> 2;
    const int t0  = (blockIdx.x & 3) * 2048;
    const int ts  = max(t0 - WARM, 0);
    const int ts2 = max(ts - 1, 0);
    const int E   = t0 + 2048 - ts;
    const int NG  = t0 + 2048 - ts2;
    const int hof = ts - ts2;                          // 0 or 1

    const float2* gz = reinterpret_cast<const float2*>(gaze) + (size_t)row * T_;
    for (int i = tid; i < NG; i += 256) sg[i] = gz[ts2 + i];
    const float thr  = expf(p_logthr[0]);
    const float invT = p_invT[0];
    const float inv_dt = 240.0f;
    __syncthreads();

    const int CH = (E + 255) >> 8;                     // 8 or 10
    float Af = 1.0f, Bf = 0.0f, As = 1.0f, Bs = 0.0f;
    for (int i = 0; i < CH; i++) {
        int e = tid * CH + i;
        if (e < E) {
            int j = e + hof;
            float2 xc = sg[j];
            float2 x1 = sg[max(j - 1, 0)];
            float vx = (xc.x - x1.x) * inv_dt;
            float vy = (xc.y - x1.y) * inv_dt;
            float sp = sqrtf(vx * vx + vy * vy);
            float g  = 1.0f / (1.0f + expf(-invT * (sp - thr)));
            sga[e] = g;
            Bf = 0.8f  * Bf + 0.2f  * g;  Af *= 0.8f;
            Bs = 0.95f * Bs + 0.05f * g;  As *= 0.95f;
        }
    }
    // block affine scan (8 warps)
    const unsigned full = 0xffffffffu;
    const int lane = tid & 31, warp = tid >> 5;
    float iAf = Af, iBf = Bf, iAs = As, iBs = Bs;
#pragma unroll
    for (int d = 1; d < 32; d <<= 1) {
        float pa = __shfl_up_sync(full, iAf, d);
        float pb = __shfl_up_sync(full, iBf, d);
        float qa = __shfl_up_sync(full, iAs, d);
        float qb = __shfl_up_sync(full, iBs, d);
        if (lane >= d) {
            iBf = iAf * pb + iBf;  iAf *= pa;
            iBs = iAs * qb + iBs;  iAs *= qa;
        }
    }
    float eAf = __shfl_up_sync(full, iAf, 1), eBf = __shfl_up_sync(full, iBf, 1);
    float eAs = __shfl_up_sync(full, iAs, 1), eBs = __shfl_up_sync(full, iBs, 1);
    if (lane == 0) { eAf = 1.0f; eBf = 0.0f; eAs = 1.0f; eBs = 0.0f; }
    if (lane == 31) {
        scn[warp] = iAf; scn[8 + warp] = iBf; scn[16 + warp] = iAs; scn[24 + warp] = iBs;
    }
    __syncthreads();
    float pBf = 0.0f, pBs = 0.0f;
    for (int w = 0; w < warp; w++) {
        pBf = scn[w] * pBf + scn[8 + w];
        pBs = scn[16 + w] * pBs + scn[24 + w];
    }
    float accf = eAf * pBf + eBf;
    float accs = eAs * pBs + eBs;
    for (int i = 0; i < CH; i++) {
        int e = tid * CH + i;
        if (e < E) {
            float g = sga[e];
            accf = 0.8f  * accf + 0.2f  * g;
            accs = 0.95f * accs + 0.05f * g;
            sqf[e] = accf; sqs[e] = accs;
        }
    }
    __syncthreads();
    const size_t base = (size_t)row * T_ + t0;
    const int off = t0 - ts;
    for (int i = tid; i < 2048; i += 256) {
        gate_o[base + i] = sga[off + i];
        qf_o[base + i]   = sqf[off + i];
        qs_o[base + i]   = sqs[off + i];
    }
}

// ---------------------------------------------------------------------------
// Kernel B: features -> gelu(X@W1+b1) -> gelu(..@W2+b2), 256-row tiles,
// 512 threads (16 warps), 3xTF32 mma.sync, split-precomputed A operands,
// h1 quartered over K (32 cols at a time).
// ---------------------------------------------------------------------------
// smem float offsets
#define SFH   0                       // fs hi  [256][20]
#define SFL   (SFH + 5120)            // fs lo
#define SW1H  (SFL + 5120)            // W1^T hi [128][20]
#define SW1L  (SW1H + 2560)           // W1^T lo
#define SW2T  (SW1L + 2560)           // W2^T fp32 [128][132]
#define SH1H  (SW2T + 16896)          // h1 hi quarter [256][36]
#define SH1L  (SH1H + 9216)           // h1 lo quarter
#define SB1   (SH1L + 9216)           // 128
#define SB2   (SB1 + 128)             // 128
#define SMEMF (SB2 + 128)             // 50944 floats = 203776 B

__global__ void __launch_bounds__(512, 1) mlp_kernel(
    const float* __restrict__ gaze,
    const float* __restrict__ lwx, const float* __restrict__ phx,
    const float* __restrict__ lwy, const float* __restrict__ phy,
    const float* __restrict__ gate_i, const float* __restrict__ qf_i,
    const float* __restrict__ qs_i,
    const float* __restrict__ W1, const float* __restrict__ b1,
    const float* __restrict__ W2, const float* __restrict__ b2,
    float* __restrict__ out)
{
    extern __shared__ float sm[];
    float* fsh  = sm + SFH;
    float* fsl  = sm + SFL;
    float* w1h  = sm + SW1H;
    float* w1l  = sm + SW1L;
    float* w2t  = sm + SW2T;
    float* h1h  = sm + SH1H;
    float* h1l  = sm + SH1L;
    float* b1s  = sm + SB1;
    float* b2s  = sm + SB2;

    const int tid  = threadIdx.x;
    const int bIdx = blockIdx.x >> 5;          // batch row
    const int t0   = (blockIdx.x & 31) << 8;   // tile start (256 steps)

    // ---- cooperative weight staging ----
    for (int i = tid; i < 16384; i += 512) {   // W2 transposed: w2t[c][k]
        int k = i >> 7, c = i & 127;
        w2t[c * 132 + k] = W2[i];
    }
    for (int i = tid; i < 2560; i += 512) {    // W1 transposed + split
        int c = i / 20, k = i - 20 * c;
        unsigned h, l; split_tf32(W1[k * 128 + c], h, l);
        w1h[i] = __uint_as_float(h); w1l[i] = __uint_as_float(l);
    }
    if (tid < 128) { b1s[tid] = b1[tid]; b2s[tid] = b2[tid]; }

    // ---- features (threads 0..255, one timestep each) ----
    if (tid < 256) {
        const float2* gz = reinterpret_cast<const float2*>(gaze) + (size_t)bIdx * T_;
        const int t = t0 + tid;
        const size_t idx = (size_t)bIdx * T_ + t;
        float2 xc = gz[t];
        float2 x1 = gz[max(t - 1, 0)];
        float2 x2 = gz[max(t - 2, 0)];
        const float inv_dt = 240.0f;
        float vx  = (xc.x - x1.x) * inv_dt;
        float vy  = (xc.y - x1.y) * inv_dt;
        float pvx = (x1.x - x2.x) * inv_dt;
        float pvy = (x1.y - x2.y) * inv_dt;
        float ax  = (vx - pvx) * inv_dt;
        float ay  = (vy - pvy) * inv_dt;
        float sp  = sqrtf(vx * vx + vy * vy);
        float isp = 1.0f / (sp + 1e-6f);
        const float twopi = 6.283185307179586f;
        float wx0 = expf(lwx[0]), wx1 = expf(lwx[1]);
        float wy0 = expf(lwy[0]), wy1 = expf(lwy[1]);
        float f[20];
        float s0, c0, s1, c1, u0, d0, u1, d1;
        sincosf(twopi * xc.x * wx0 + phx[0], &s0, &c0);
        sincosf(twopi * xc.x * wx1 + phx[1], &s1, &c1);
        sincosf(twopi * xc.y * wy0 + phy[0], &u0, &d0);
        sincosf(twopi * xc.y * wy1 + phy[1], &u1, &d1);
        f[0]=s0; f[1]=s1; f[2]=c0; f[3]=c1; f[4]=u0; f[5]=u1; f[6]=d0; f[7]=d1;
        f[8]=vx; f[9]=vy; f[10]=sp; f[11]=vx*isp; f[12]=vy*isp;
        f[13]=ax; f[14]=ay;
        f[15]=(vx*ax+vy*ay)*isp; f[16]=(vx*ay-vy*ax)*isp;
        f[17]=gate_i[idx]; f[18]=qf_i[idx]; f[19]=qs_i[idx];
#pragma unroll
        for (int j = 0; j < 20; j++) {
            unsigned h, l; split_tf32(f[j], h, l);
            fsh[tid * 20 + j] = __uint_as_float(h);
            fsl[tid * 20 + j] = __uint_as_float(l);
        }
    }
    __syncthreads();

    // ---- MLP, 16 warps: wm = M quarter (64 rows), wn = N group (32 cols) ----
    const int lane = tid & 31, warp = tid >> 5;
    const int g = lane >> 2, tg = lane & 3;
    const int wm = warp >> 2, wn = warp & 3;

    float acc2[16][4];
#pragma unroll
    for (int mt = 0; mt < 4; mt++)
#pragma unroll
        for (int nt = 0; nt < 4; nt++) {
            int f = mt * 4 + nt, col = wn * 32 + nt * 8 + 2 * tg;
            acc2[f][0] = b2s[col];  acc2[f][1] = b2s[col + 1];
            acc2[f][2] = acc2[f][0]; acc2[f][3] = acc2[f][1];
        }

#pragma unroll 1
    for (int q = 0; q < 4; q++) {
        // ===== stage 1: h1 quarter cols [q*32, q*32+32) =====
        const int c1 = q * 32 + wn * 8;         // this warp's global h1 col base
        float acc1[4][4];
#pragma unroll
        for (int mt = 0; mt < 4; mt++) {
            acc1[mt][0] = b1s[c1 + 2 * tg]; acc1[mt][1] = b1s[c1 + 2 * tg + 1];
            acc1[mt][2] = acc1[mt][0];      acc1[mt][3] = acc1[mt][1];
        }
#pragma unroll
        for (int kc = 0; kc < 2; kc++) {        // K chunks of 8
            int k0 = kc * 8;
            unsigned Bh[2], Bl[2];
            int ba = (c1 + g) * 20 + k0 + tg;
            Bh[0] = __float_as_uint(w1h[ba]);     Bl[0] = __float_as_uint(w1l[ba]);
            Bh[1] = __float_as_uint(w1h[ba + 4]); Bl[1] = __float_as_uint(w1l[ba + 4]);
#pragma unroll
            for (int mt = 0; mt < 4; mt++) {
                int r = wm * 64 + mt * 16 + g;
                int aa = r * 20 + k0 + tg;
                unsigned Ah[4], Al[4];
                Ah[0] = __float_as_uint(fsh[aa]);            Al[0] = __float_as_uint(fsl[aa]);
                Ah[1] = __float_as_uint(fsh[aa + 8 * 20]);   Al[1] = __float_as_uint(fsl[aa + 8 * 20]);
                Ah[2] = __float_as_uint(fsh[aa + 4]);        Al[2] = __float_as_uint(fsl[aa + 4]);
                Ah[3] = __float_as_uint(fsh[aa + 8 * 20 + 4]); Al[3] = __float_as_uint(fsl[aa + 8 * 20 + 4]);
                MMA8(acc1[mt], Ah, Bh);
                MMA8(acc1[mt], Ah, Bl);
                MMA8(acc1[mt], Al, Bh);
            }
        }
        {   // K chunk of 4 (k = 16..19)
            unsigned Bh1[1], Bl1[1];
            int ba = (c1 + g) * 20 + 16 + tg;
            Bh1[0] = __float_as_uint(w1h[ba]); Bl1[0] = __float_as_uint(w1l[ba]);
#pragma unroll
            for (int mt = 0; mt < 4; mt++) {
                int r = wm * 64 + mt * 16 + g;
                int aa = r * 20 + 16 + tg;
                unsigned Ah[2], Al[2];
                Ah[0] = __float_as_uint(fsh[aa]);          Al[0] = __float_as_uint(fsl[aa]);
                Ah[1] = __float_as_uint(fsh[aa + 8 * 20]); Al[1] = __float_as_uint(fsl[aa + 8 * 20]);
                MMA4(acc1[mt], Ah, Bh1);
                MMA4(acc1[mt], Ah, Bl1);
                MMA4(acc1[mt], Al, Bh1);
            }
        }
        // epilogue: gelu + split-store into quarter buffer (local cols)
#pragma unroll
        for (int mt = 0; mt < 4; mt++) {
            int r = wm * 64 + mt * 16 + g;
            int cc = wn * 8 + 2 * tg;
            unsigned h, l;
            float v0 = gelu_exact(acc1[mt][0]);
            float v1 = gelu_exact(acc1[mt][1]);
            float v2 = gelu_exact(acc1[mt][2]);
            float v3 = gelu_exact(acc1[mt][3]);
            split_tf32(v0, h, l); h1h[r*36+cc]   = __uint_as_float(h); h1l[r*36+cc]   = __uint_as_float(l);
            split_tf32(v1, h, l); h1h[r*36+cc+1] = __uint_as_float(h); h1l[r*36+cc+1] = __uint_as_float(l);
            split_tf32(v2, h, l); h1h[(r+8)*36+cc]   = __uint_as_float(h); h1l[(r+8)*36+cc]   = __uint_as_float(l);
            split_tf32(v3, h, l); h1h[(r+8)*36+cc+1] = __uint_as_float(h); h1l[(r+8)*36+cc+1] = __uint_as_float(l);
        }
        __syncthreads();

        // ===== stage 2: accumulate K slice [q*32, q*32+32) =====
#pragma unroll
        for (int kc = 0; kc < 4; kc++) {
            int k0 = kc * 8;
            unsigned Bb[4][2], Bl2[4][2];
#pragma unroll
            for (int nt = 0; nt < 4; nt++) {
                int c = wn * 32 + nt * 8 + g;
                int ad = c * 132 + q * 32 + k0 + tg;
                split_tf32(w2t[ad],     Bb[nt][0], Bl2[nt][0]);
                split_tf32(w2t[ad + 4], Bb[nt][1], Bl2[nt][1]);
            }
#pragma unroll
            for (int mt = 0; mt < 4; mt++) {
                int r = wm * 64 + mt * 16 + g;
                int ad = r * 36 + k0 + tg;
                unsigned Ah[4], Al[4];
                Ah[0] = __float_as_uint(h1h[ad]);            Al[0] = __float_as_uint(h1l[ad]);
                Ah[1] = __float_as_uint(h1h[ad + 8 * 36]);   Al[1] = __float_as_uint(h1l[ad + 8 * 36]);
                Ah[2] = __float_as_uint(h1h[ad + 4]);        Al[2] = __float_as_uint(h1l[ad + 4]);
                Ah[3] = __float_as_uint(h1h[ad + 8 * 36 + 4]); Al[3] = __float_as_uint(h1l[ad + 8 * 36 + 4]);
#pragma unroll
                for (int nt = 0; nt < 4; nt++) {
                    int f = mt * 4 + nt;
                    MMA8(acc2[f], Ah, Bb[nt]);
                    MMA8(acc2[f], Ah, Bl2[nt]);
                    MMA8(acc2[f], Al, Bb[nt]);
                }
            }
        }
        __syncthreads();
    }

    // ---- final epilogue ----
    const size_t r0 = (size_t)blockIdx.x * 256;
#pragma unroll
    for (int mt = 0; mt < 4; mt++)
#pragma unroll
        for (int nt = 0; nt < 4; nt++) {
            int f = mt * 4 + nt;
            int r = wm * 64 + mt * 16 + g;
            int c = wn * 32 + nt * 8 + 2 * tg;
            float2 v0 = make_float2(gelu_exact(acc2[f][0]), gelu_exact(acc2[f][1]));
            float2 v1 = make_float2(gelu_exact(acc2[f][2]), gelu_exact(acc2[f][3]));
            *reinterpret_cast<float2*>(out + (r0 + r) * 128 + c)     = v0;
            *reinterpret_cast<float2*>(out + (r0 + r + 8) * 128 + c) = v1;
        }
}

// ---------------------------------------------------------------------------
extern "C" void kernel_launch(void* const* d_in, const int* in_sizes, int n_in,
                              void* d_out, int out_size)
{
    const float* gaze   = (const float*)d_in[0];
    const float* lwx    = (const float*)d_in[1];
    const float* phx    = (const float*)d_in[2];
    const float* lwy    = (const float*)d_in[3];
    const float* phy    = (const float*)d_in[4];
    const float* logthr = (const float*)d_in[5];
    const float* invT   = (const float*)d_in[6];
    const float* W1     = (const float*)d_in[7];
    const float* b1     = (const float*)d_in[8];
    const float* W2     = (const float*)d_in[9];
    const float* b2     = (const float*)d_in[10];
    float* out = (float*)d_out;

    float *gate, *qf, *qs;
    cudaGetSymbolAddress((void**)&gate, g_gate);
    cudaGetSymbolAddress((void**)&qf,   g_qf);
    cudaGetSymbolAddress((void**)&qs,   g_qs);

    const size_t smemA = (size_t)(5124 + 3 * 2560 + 32) * sizeof(float); // 51344 B
    cudaFuncSetAttribute(ema_kernel,
                         cudaFuncAttributeMaxDynamicSharedMemorySize, (int)smemA);
    ema_kernel<<<B_ * 4, 256, smemA>>>(gaze, logthr, invT, gate, qf, qs);

    const size_t smemB = (size_t)SMEMF * sizeof(float);                  // 203776 B
    cudaFuncSetAttribute(mlp_kernel,
                         cudaFuncAttributeMaxDynamicSharedMemorySize, (int)smemB);
    mlp_kernel<<<(int)(NROWS / 256), 512, smemB>>>(
        gaze, lwx, phx, lwy, phy, gate, qf, qs, W1, b1, W2, b2, out);
}

// round 6
// speedup vs baseline: 2.9866x; 1.5917x over previous
#include <cuda_runtime.h>
#include <cuda_bf16.h>
#include <stdint.h>
#include <math.h>

#define B_    64
#define T_    8192
#define DIN   20
#define DOUT  128
#define NROWS ((size_t)B_ * T_)
#define WARM  512

// device scratch
__device__ float g_gate[NROWS];
__device__ float g_qf[NROWS];
__device__ float g_qs[NROWS];
// pre-split weight planes (bf16 hi/lo), padded layouts
// W1^T: [n=128][k=24]   W2^T: [n=128][k=136]
__device__ __align__(16) __nv_bfloat16 g_w1h[128 * 24];
__device__ __align__(16) __nv_bfloat16 g_w1l[128 * 24];
__device__ __align__(16) __nv_bfloat16 g_w2h[128 * 136];
__device__ __align__(16) __nv_bfloat16 g_w2l[128 * 136];

// ---------------------------------------------------------------------------
__device__ __forceinline__ void mma16(float* d, const uint32_t* a, const uint32_t* b) {
    asm volatile(
        "mma.sync.aligned.m16n8k16.row.col.f32.bf16.bf16.f32 "
        "{%0,%1,%2,%3}, {%4,%5,%6,%7}, {%8,%9}, {%0,%1,%2,%3};"
        : "+f"(d[0]), "+f"(d[1]), "+f"(d[2]), "+f"(d[3])
        : "r"(a[0]), "r"(a[1]), "r"(a[2]), "r"(a[3]), "r"(b[0]), "r"(b[1]));
}
__device__ __forceinline__ void mma8b(float* d, const uint32_t* a, const uint32_t* b) {
    asm volatile(
        "mma.sync.aligned.m16n8k8.row.col.f32.bf16.bf16.f32 "
        "{%0,%1,%2,%3}, {%4,%5}, {%6}, {%0,%1,%2,%3};"
        : "+f"(d[0]), "+f"(d[1]), "+f"(d[2]), "+f"(d[3])
        : "r"(a[0]), "r"(a[1]), "r"(b[0]));
}
__device__ __forceinline__ void ldsm4(uint32_t* R, uint32_t addr) {
    asm volatile("ldmatrix.sync.aligned.m8n8.x4.shared.b16 {%0,%1,%2,%3},[%4];"
        : "=r"(R[0]), "=r"(R[1]), "=r"(R[2]), "=r"(R[3]) : "r"(addr));
}
__device__ __forceinline__ void ldsm2(uint32_t* R, uint32_t addr) {
    asm volatile("ldmatrix.sync.aligned.m8n8.x2.shared.b16 {%0,%1},[%2];"
        : "=r"(R[0]), "=r"(R[1]) : "r"(addr));
}
__device__ __forceinline__ void ldsm1(uint32_t* R, uint32_t addr) {
    asm volatile("ldmatrix.sync.aligned.m8n8.x1.shared.b16 {%0},[%1];"
        : "=r"(R[0]) : "r"(addr));
}
__device__ __forceinline__ void cpasync16(uint32_t saddr, const void* g) {
    asm volatile("cp.async.cg.shared.global [%0], [%1], 16;"
                 :: "r"(saddr), "l"(g));
}
__device__ __forceinline__ float gelu_exact(float x) {
    return 0.5f * x * (1.0f + erff(x * 0.70710678118654752f));
}
// pack (x0 -> lower bf16, x1 -> upper) hi plane and residual lo plane
__device__ __forceinline__ void split2_bf16(float x0, float x1,
                                            uint32_t& hi, uint32_t& lo) {
    uint32_t h;
    asm("cvt.rn.bf16x2.f32 %0, %1, %2;" : "=r"(h) : "f"(x1), "f"(x0));
    float h0 = __uint_as_float(h << 16);
    float h1 = __uint_as_float(h & 0xffff0000u);
    float r0 = x0 - h0, r1 = x1 - h1;
    asm("cvt.rn.bf16x2.f32 %0, %1, %2;" : "=r"(lo) : "f"(r1), "f"(r0));
    hi = h;
}

// ---------------------------------------------------------------------------
// Prep kernel: split W1/W2 into bf16 hi/lo transposed padded planes.
// ---------------------------------------------------------------------------
__global__ void prep_kernel(const float* __restrict__ W1,
                            const float* __restrict__ W2)
{
    int i = blockIdx.x * 256 + threadIdx.x;
    if (i < 128 * 136) {
        int n = i / 136, k = i - n * 136;
        float v = (k < 128) ? W2[k * 128 + n] : 0.0f;
        __nv_bfloat16 h = __float2bfloat16_rn(v);
        g_w2h[i] = h;
        g_w2l[i] = __float2bfloat16_rn(v - __bfloat162float(h));
    }
    if (i < 128 * 24) {
        int n = i / 24, k = i - n * 24;
        float v = (k < DIN) ? W1[k * 128 + n] : 0.0f;
        __nv_bfloat16 h = __float2bfloat16_rn(v);
        g_w1h[i] = h;
        g_w1l[i] = __float2bfloat16_rn(v - __bfloat162float(h));
    }
}

// ---------------------------------------------------------------------------
// Kernel A: gate + EMA(0.8/0.95) with 512-step warm-up, segment-parallel.
// ---------------------------------------------------------------------------
__global__ void __launch_bounds__(256) ema_kernel(
    const float* __restrict__ gaze,
    const float* __restrict__ p_logthr, const float* __restrict__ p_invT,
    float* __restrict__ gate_o, float* __restrict__ qf_o, float* __restrict__ qs_o)
{
    extern __shared__ float sm[];
    float2* sg  = reinterpret_cast<float2*>(sm);
    float*  sga = sm + 5124;
    float*  sqf = sga + 2560;
    float*  sqs = sqf + 2560;
    float*  scn = sqs + 2560;

    const int tid = threadIdx.x;
    const int row = blockIdx.x >> 2;
    const int t0  = (blockIdx.x & 3) * 2048;
    const int ts  = max(t0 - WARM, 0);
    const int ts2 = max(ts - 1, 0);
    const int E   = t0 + 2048 - ts;
    const int NG  = t0 + 2048 - ts2;
    const int hof = ts - ts2;

    const float2* gz = reinterpret_cast<const float2*>(gaze) + (size_t)row * T_;
    for (int i = tid; i < NG; i += 256) sg[i] = gz[ts2 + i];
    const float thr  = expf(p_logthr[0]);
    const float invT = p_invT[0];
    const float inv_dt = 240.0f;
    __syncthreads();

    const int CH = (E + 255) >> 8;
    float Af = 1.0f, Bf = 0.0f, As = 1.0f, Bs = 0.0f;
    for (int i = 0; i < CH; i++) {
        int e = tid * CH + i;
        if (e < E) {
            int j = e + hof;
            float2 xc = sg[j];
            float2 x1 = sg[max(j - 1, 0)];
            float vx = (xc.x - x1.x) * inv_dt;
            float vy = (xc.y - x1.y) * inv_dt;
            float sp = sqrtf(vx * vx + vy * vy);
            float g  = 1.0f / (1.0f + expf(-invT * (sp - thr)));
            sga[e] = g;
            Bf = 0.8f  * Bf + 0.2f  * g;  Af *= 0.8f;
            Bs = 0.95f * Bs + 0.05f * g;  As *= 0.95f;
        }
    }
    const unsigned full = 0xffffffffu;
    const int lane = tid & 31, warp = tid >> 5;
    float iAf = Af, iBf = Bf, iAs = As, iBs = Bs;
#pragma unroll
    for (int d = 1; d < 32; d <<= 1) {
        float pa = __shfl_up_sync(full, iAf, d);
        float pb = __shfl_up_sync(full, iBf, d);
        float qa = __shfl_up_sync(full, iAs, d);
        float qb = __shfl_up_sync(full, iBs, d);
        if (lane >= d) {
            iBf = iAf * pb + iBf;  iAf *= pa;
            iBs = iAs * qb + iBs;  iAs *= qa;
        }
    }
    float eAf = __shfl_up_sync(full, iAf, 1), eBf = __shfl_up_sync(full, iBf, 1);
    float eAs = __shfl_up_sync(full, iAs, 1), eBs = __shfl_up_sync(full, iBs, 1);
    if (lane == 0) { eAf = 1.0f; eBf = 0.0f; eAs = 1.0f; eBs = 0.0f; }
    if (lane == 31) {
        scn[warp] = iAf; scn[8 + warp] = iBf; scn[16 + warp] = iAs; scn[24 + warp] = iBs;
    }
    __syncthreads();
    float pBf = 0.0f, pBs = 0.0f;
    for (int w = 0; w < warp; w++) {
        pBf = scn[w] * pBf + scn[8 + w];
        pBs = scn[16 + w] * pBs + scn[24 + w];
    }
    float accf = eAf * pBf + eBf;
    float accs = eAs * pBs + eBs;
    for (int i = 0; i < CH; i++) {
        int e = tid * CH + i;
        if (e < E) {
            float g = sga[e];
            accf = 0.8f  * accf + 0.2f  * g;
            accs = 0.95f * accs + 0.05f * g;
            sqf[e] = accf; sqs[e] = accs;
        }
    }
    __syncthreads();
    const size_t base = (size_t)row * T_ + t0;
    const int off = t0 - ts;
    for (int i = tid; i < 2048; i += 256) {
        gate_o[base + i] = sga[off + i];
        qf_o[base + i]   = sqf[off + i];
        qs_o[base + i]   = sqs[off + i];
    }
}

// ---------------------------------------------------------------------------
// Main kernel: 128-row tiles, 512 threads (16 warps), bf16x3 + ldmatrix.
// ---------------------------------------------------------------------------
// smem byte offsets
#define SM_FSH 0                     // feats hi  [128][24] bf16 = 6144
#define SM_FSL 6144
#define SM_W1H 12288                 // W1^T hi [128][24] bf16 = 6144
#define SM_W1L 18432
#define SM_W2H 24576                 // W2^T hi [128][136] bf16 = 34816
#define SM_W2L 59392
#define SM_H1H 94208                 // h1 hi [128][136] bf16 = 34816
#define SM_H1L 129024
#define SM_B1  163840                // 512
#define SM_B2  164352                // 512
#define SM_TOT 164864

__global__ void __launch_bounds__(512, 1) mlp_kernel(
    const float* __restrict__ gaze,
    const float* __restrict__ lwx, const float* __restrict__ phx,
    const float* __restrict__ lwy, const float* __restrict__ phy,
    const float* __restrict__ gate_i, const float* __restrict__ qf_i,
    const float* __restrict__ qs_i,
    const float* __restrict__ b1, const float* __restrict__ b2,
    float* __restrict__ out)
{
    extern __shared__ char smem[];
    const uint32_t sbase = (uint32_t)__cvta_generic_to_shared(smem);
    uint32_t* fshw = reinterpret_cast<uint32_t*>(smem + SM_FSH);
    uint32_t* fslw = reinterpret_cast<uint32_t*>(smem + SM_FSL);
    uint32_t* h1hw = reinterpret_cast<uint32_t*>(smem + SM_H1H);
    uint32_t* h1lw = reinterpret_cast<uint32_t*>(smem + SM_H1L);
    float* b1s = reinterpret_cast<float*>(smem + SM_B1);
    float* b2s = reinterpret_cast<float*>(smem + SM_B2);

    const int tid  = threadIdx.x;
    const int bIdx = blockIdx.x >> 6;
    const int t0   = (blockIdx.x & 63) << 7;   // 128-step tile

    // ---- async weight staging (pre-split bf16 planes) ----
    {
        const char* s2h = (const char*)g_w2h;
        const char* s2l = (const char*)g_w2l;
        for (int c = tid; c < 2176; c += 512) {
            cpasync16(sbase + SM_W2H + c * 16, s2h + c * 16);
            cpasync16(sbase + SM_W2L + c * 16, s2l + c * 16);
        }
        const char* s1h = (const char*)g_w1h;
        const char* s1l = (const char*)g_w1l;
        if (tid < 384) {
            cpasync16(sbase + SM_W1H + tid * 16, s1h + tid * 16);
            cpasync16(sbase + SM_W1L + tid * 16, s1l + tid * 16);
        }
        asm volatile("cp.async.commit_group;");
    }
    if (tid < 128) { b1s[tid] = b1[tid]; b2s[tid] = b2[tid]; }

    // ---- features: threads 0..127, one timestep each ----
    if (tid < 128) {
        const float2* gz = reinterpret_cast<const float2*>(gaze) + (size_t)bIdx * T_;
        const int t = t0 + tid;
        const size_t idx = (size_t)bIdx * T_ + t;
        float2 xc = gz[t];
        float2 x1 = gz[max(t - 1, 0)];
        float2 x2 = gz[max(t - 2, 0)];
        const float inv_dt = 240.0f;
        float vx  = (xc.x - x1.x) * inv_dt;
        float vy  = (xc.y - x1.y) * inv_dt;
        float pvx = (x1.x - x2.x) * inv_dt;
        float pvy = (x1.y - x2.y) * inv_dt;
        float ax  = (vx - pvx) * inv_dt;
        float ay  = (vy - pvy) * inv_dt;
        float sp  = sqrtf(vx * vx + vy * vy);
        float isp = 1.0f / (sp + 1e-6f);
        const float twopi = 6.283185307179586f;
        float wx0 = expf(lwx[0]), wx1 = expf(lwx[1]);
        float wy0 = expf(lwy[0]), wy1 = expf(lwy[1]);
        float f[20];
        float s0, c0, s1, c1, u0, d0, u1, d1;
        sincosf(twopi * xc.x * wx0 + phx[0], &s0, &c0);
        sincosf(twopi * xc.x * wx1 + phx[1], &s1, &c1);
        sincosf(twopi * xc.y * wy0 + phy[0], &u0, &d0);
        sincosf(twopi * xc.y * wy1 + phy[1], &u1, &d1);
        f[0]=s0; f[1]=s1; f[2]=c0; f[3]=c1; f[4]=u0; f[5]=u1; f[6]=d0; f[7]=d1;
        f[8]=vx; f[9]=vy; f[10]=sp; f[11]=vx*isp; f[12]=vy*isp;
        f[13]=ax; f[14]=ay;
        f[15]=(vx*ax+vy*ay)*isp; f[16]=(vx*ay-vy*ax)*isp;
        f[17]=gate_i[idx]; f[18]=qf_i[idx]; f[19]=qs_i[idx];
#pragma unroll
        for (int j = 0; j < 10; j++) {
            uint32_t hi, lo;
            split2_bf16(f[2 * j], f[2 * j + 1], hi, lo);
            fshw[tid * 12 + j] = hi;
            fslw[tid * 12 + j] = lo;
        }
        fshw[tid * 12 + 10] = 0; fshw[tid * 12 + 11] = 0;  // K pad 20..23
        fslw[tid * 12 + 10] = 0; fslw[tid * 12 + 11] = 0;
    }
    asm volatile("cp.async.wait_group 0;");
    __syncthreads();

    const int lane = tid & 31, warp = tid >> 5;
    const int g  = lane >> 2, tg = lane & 3;
    const int wm = warp >> 2, wn = warp & 3;

    // ldmatrix lane-address components
    const int t4  = lane >> 3;
    const int tr4 = lane & 7;
    const int r4  = (t4 & 1) * 8 + tr4;           // A x4: row offset
    const int k4  = (t4 >> 1) * 16;               // A x4: k-byte offset
    const int r2  = ((lane >> 3) & 1) * 8 + tr4;  // A x2 row
    const int rB4 = lane & 7;                     // B x4 n row
    const int kB4 = t4 * 16;                      // B x4 k-byte per tile

    // ================= Stage 1: h1 = gelu(feats @ W1 + b1) =================
    float acc1[2][4][4];
#pragma unroll
    for (int mt = 0; mt < 2; mt++)
#pragma unroll
        for (int nt = 0; nt < 4; nt++) {
            int col = wn * 32 + nt * 8 + 2 * tg;
            acc1[mt][nt][0] = b1s[col];     acc1[mt][nt][1] = b1s[col + 1];
            acc1[mt][nt][2] = b1s[col];     acc1[mt][nt][3] = b1s[col + 1];
        }

    uint32_t A1h[2][6], A1l[2][6];
#pragma unroll
    for (int mt = 0; mt < 2; mt++) {
        int rA = wm * 32 + mt * 16;
        ldsm4(&A1h[mt][0], sbase + SM_FSH + (rA + r4) * 48 + k4);
        ldsm4(&A1l[mt][0], sbase + SM_FSL + (rA + r4) * 48 + k4);
        ldsm2(&A1h[mt][4], sbase + SM_FSH + (rA + r2) * 48 + 32);
        ldsm2(&A1l[mt][4], sbase + SM_FSL + (rA + r2) * 48 + 32);
    }
#pragma unroll
    for (int nt = 0; nt < 4; nt++) {
        int nB = wn * 32 + nt * 8;
        uint32_t B1h[3], B1l[3];
        ldsm2(&B1h[0], sbase + SM_W1H + (nB + tr4) * 48 + ((lane >> 3) & 1) * 16);
        ldsm2(&B1l[0], sbase + SM_W1L + (nB + tr4) * 48 + ((lane >> 3) & 1) * 16);
        ldsm1(&B1h[2], sbase + SM_W1H + (nB + tr4) * 48 + 32);
        ldsm1(&B1l[2], sbase + SM_W1L + (nB + tr4) * 48 + 32);
#pragma unroll
        for (int mt = 0; mt < 2; mt++) {
            mma16(acc1[mt][nt], &A1h[mt][0], &B1h[0]);
            mma16(acc1[mt][nt], &A1h[mt][0], &B1l[0]);
            mma16(acc1[mt][nt], &A1l[mt][0], &B1h[0]);
            mma8b(acc1[mt][nt], &A1h[mt][4], &B1h[2]);
            mma8b(acc1[mt][nt], &A1h[mt][4], &B1l[2]);
            mma8b(acc1[mt][nt], &A1l[mt][4], &B1h[2]);
        }
    }

    // stage-1 epilogue: gelu + bf16 split into h1 planes
#pragma unroll
    for (int mt = 0; mt < 2; mt++)
#pragma unroll
        for (int nt = 0; nt < 4; nt++) {
            int row = wm * 32 + mt * 16 + g;
            int col = wn * 32 + nt * 8 + 2 * tg;
            uint32_t hi, lo;
            split2_bf16(gelu_exact(acc1[mt][nt][0]), gelu_exact(acc1[mt][nt][1]), hi, lo);
            h1hw[row * 68 + (col >> 1)] = hi;
            h1lw[row * 68 + (col >> 1)] = lo;
            split2_bf16(gelu_exact(acc1[mt][nt][2]), gelu_exact(acc1[mt][nt][3]), hi, lo);
            h1hw[(row + 8) * 68 + (col >> 1)] = hi;
            h1lw[(row + 8) * 68 + (col >> 1)] = lo;
        }
    __syncthreads();

    // ================= Stage 2: out = gelu(h1 @ W2 + b2) =================
    float acc2[2][4][4];
#pragma unroll
    for (int mt = 0; mt < 2; mt++)
#pragma unroll
        for (int nt = 0; nt < 4; nt++) {
            int col = wn * 32 + nt * 8 + 2 * tg;
            acc2[mt][nt][0] = b2s[col];     acc2[mt][nt][1] = b2s[col + 1];
            acc2[mt][nt][2] = b2s[col];     acc2[mt][nt][3] = b2s[col + 1];
        }

#pragma unroll 1
    for (int kc2 = 0; kc2 < 4; kc2++) {           // 32 K per iter
        uint32_t Bh[4][4], Bl[4][4];
#pragma unroll
        for (int nt = 0; nt < 4; nt++) {
            int nB = wn * 32 + nt * 8 + rB4;
            ldsm4(Bh[nt], sbase + SM_W2H + nB * 272 + kc2 * 64 + kB4);
            ldsm4(Bl[nt], sbase + SM_W2L + nB * 272 + kc2 * 64 + kB4);
        }
        uint32_t Ah[2][2][4], Al[2][2][4];
#pragma unroll
        for (int mt = 0; mt < 2; mt++) {
            int rA = wm * 32 + mt * 16 + r4;
#pragma unroll
            for (int s = 0; s < 2; s++) {
                ldsm4(Ah[mt][s], sbase + SM_H1H + rA * 272 + kc2 * 64 + s * 32 + k4);
                ldsm4(Al[mt][s], sbase + SM_H1L + rA * 272 + kc2 * 64 + s * 32 + k4);
            }
        }
#pragma unroll
        for (int mt = 0; mt < 2; mt++)
#pragma unroll
            for (int nt = 0; nt < 4; nt++)
#pragma unroll
                for (int s = 0; s < 2; s++) {
                    mma16(acc2[mt][nt], Ah[mt][s], &Bh[nt][2 * s]);
                    mma16(acc2[mt][nt], Ah[mt][s], &Bl[nt][2 * s]);
                    mma16(acc2[mt][nt], Al[mt][s], &Bh[nt][2 * s]);
                }
    }

    // final epilogue
    const size_t r0 = (size_t)blockIdx.x * 128;
#pragma unroll
    for (int mt = 0; mt < 2; mt++)
#pragma unroll
        for (int nt = 0; nt < 4; nt++) {
            int r = wm * 32 + mt * 16 + g;
            int c = wn * 32 + nt * 8 + 2 * tg;
            float2 v0 = make_float2(gelu_exact(acc2[mt][nt][0]), gelu_exact(acc2[mt][nt][1]));
            float2 v1 = make_float2(gelu_exact(acc2[mt][nt][2]), gelu_exact(acc2[mt][nt][3]));
            *reinterpret_cast<float2*>(out + (r0 + r) * 128 + c)     = v0;
            *reinterpret_cast<float2*>(out + (r0 + r + 8) * 128 + c) = v1;
        }
}

// ---------------------------------------------------------------------------
extern "C" void kernel_launch(void* const* d_in, const int* in_sizes, int n_in,
                              void* d_out, int out_size)
{
    const float* gaze   = (const float*)d_in[0];
    const float* lwx    = (const float*)d_in[1];
    const float* phx    = (const float*)d_in[2];
    const float* lwy    = (const float*)d_in[3];
    const float* phy    = (const float*)d_in[4];
    const float* logthr = (const float*)d_in[5];
    const float* invT   = (const float*)d_in[6];
    const float* W1     = (const float*)d_in[7];
    const float* b1     = (const float*)d_in[8];
    const float* W2     = (const float*)d_in[9];
    const float* b2     = (const float*)d_in[10];
    float* out = (float*)d_out;

    float *gate, *qf, *qs;
    cudaGetSymbolAddress((void**)&gate, g_gate);
    cudaGetSymbolAddress((void**)&qf,   g_qf);
    cudaGetSymbolAddress((void**)&qs,   g_qs);

    prep_kernel<<<68, 256>>>(W1, W2);

    const size_t smemA = (size_t)(5124 + 3 * 2560 + 32) * sizeof(float);
    cudaFuncSetAttribute(ema_kernel,
                         cudaFuncAttributeMaxDynamicSharedMemorySize, (int)smemA);
    ema_kernel<<<B_ * 4, 256, smemA>>>(gaze, logthr, invT, gate, qf, qs);

    cudaFuncSetAttribute(mlp_kernel,
                         cudaFuncAttributeMaxDynamicSharedMemorySize, SM_TOT);
    mlp_kernel<<<(int)(NROWS / 128), 512, SM_TOT>>>(
        gaze, lwx, phx, lwy, phy, gate, qf, qs, b1, b2, out);
}